// round 3
// baseline (speedup 1.0000x reference)
#include <cuda_runtime.h>
#include <cstdint>

#define NS 32      // samples per block
#define NT 256     // threads per block
#define FPAD 36    // padded row stride (floats) for featT / f1T / f2T (mult of 4)

// SMEM float offsets
#define OFF_WBUF 0                        // 12288 floats: fc1 dbl-buf (2x6144); also signal tile (4800) & fc2 dbl-buf (2x2048)
#define OFF_FEAT 12288                    // 12960 floats: featT[360][36] -> f1T[256][36] -> f2T[64][36]
#define OFF_SMALL (12288 + 12960)         // small consts
#define SM_FLOATS (OFF_SMALL + 1312)
#define SMBYTES (SM_FLOATS * 4)           // 106240 B -> 2 CTAs/SM

// small-const layout within OFF_SMALL
#define SW1 0      // conv1_w 45
#define SB1 45     // conv1_b 5
#define SW2 50     // conv2_w 150
#define SB2 200    // conv2_b 10
#define SFB1 210   // fc1_b 256
#define SFB2 466   // fc2_b 64
#define SPW 530    // pamap_w 768
#define SPB 1298   // pamap_b 12

typedef unsigned long long ull;

__device__ __forceinline__ ull pack2(float x, float y) {
    ull v; asm("mov.b64 %0, {%1, %2};" : "=l"(v) : "f"(x), "f"(y)); return v;
}
__device__ __forceinline__ float2 unpk(ull v) {
    float2 r; asm("mov.b64 {%0, %1}, %2;" : "=f"(r.x), "=f"(r.y) : "l"(v)); return r;
}
// duplicate scalar into packed pair (ALU pipe; avoids duplicated weights in smem)
__device__ __forceinline__ ull dup(float w) {
    ull v; asm("mov.b64 %0, {%1, %1};" : "=l"(v) : "f"(w)); return v;
}
// d = a * b + d  (packed 2x fp32, Blackwell FFMA2)
__device__ __forceinline__ void fma2(ull& d, ull a, ull b) {
    asm("fma.rn.f32x2 %0, %1, %2, %0;" : "+l"(d) : "l"(a), "l"(b));
}
// 16B shared load -> two packed f32 pairs
__device__ __forceinline__ void ld2x2(const float* p, ull& a, ull& b) {
    unsigned ad = (unsigned)__cvta_generic_to_shared(p);
    asm volatile("ld.shared.v2.u64 {%0, %1}, [%2];" : "=l"(a), "=l"(b) : "r"(ad));
}

__global__ __launch_bounds__(NT, 2)
void convnet_fused_kernel(const float* __restrict__ sig,
                          const float* __restrict__ w1, const float* __restrict__ b1,
                          const float* __restrict__ w2, const float* __restrict__ b2,
                          const float* __restrict__ fw1, const float* __restrict__ fb1,
                          const float* __restrict__ fw2, const float* __restrict__ fb2,
                          const float* __restrict__ pw, const float* __restrict__ pb,
                          float* __restrict__ out)
{
    extern __shared__ float sm[];
    const int tid = threadIdx.x;
    const int bx  = blockIdx.x;
    const int ol  = tid & 63;   // 64 output-lane groups
    const int mg  = tid >> 6;   // sample group (8 samples = 4 pairs), warp-uniform

    // ---- stage small constants ----
    for (int i = tid; i < 45;  i += NT) sm[OFF_SMALL + SW1 + i] = w1[i];
    if (tid < 5)                         sm[OFF_SMALL + SB1 + tid] = b1[tid];
    for (int i = tid; i < 150; i += NT) sm[OFF_SMALL + SW2 + i] = w2[i];
    if (tid < 10)                        sm[OFF_SMALL + SB2 + tid] = b2[tid];
    sm[OFF_SMALL + SFB1 + tid] = fb1[tid];
    if (tid < 64)                        sm[OFF_SMALL + SFB2 + tid] = fb2[tid];
    for (int i = tid; i < 768; i += NT) sm[OFF_SMALL + SPW + i] = pw[i];
    if (tid < 12)                        sm[OFF_SMALL + SPB + tid] = pb[tid];

    // ---- load signal tile: 32 samples x 150 floats ----
    {
        const float4* g = (const float4*)(sig + (size_t)bx * NS * 150);
        float4* s4 = (float4*)(sm + OFF_WBUF);
        for (int i = tid; i < NS * 150 / 4; i += NT) s4[i] = g[i];
    }
    __syncthreads();

    // ---- featurize: running_std -> conv1 -> conv2 -> featT[k][sample] ----
    {
        const int s  = tid & 31;
        const int t0 = (tid >> 5) * 5;            // 8 threads/sample, 5 t's each
        const float* xs = sm + OFF_WBUF + s * 150;

        float sd[3][9];
#pragma unroll
        for (int c = 0; c < 3; ++c) {
            float xr[18];
#pragma unroll
            for (int j = 0; j < 18; ++j) xr[j] = xs[(t0 + j) * 3 + c];
#pragma unroll
            for (int tt = 0; tt < 9; ++tt) {
                float s1 = 0.f, s2 = 0.f;
#pragma unroll
                for (int j = 0; j < 10; ++j) { float v = xr[tt + j]; s1 += v; s2 += v * v; }
                float var = (s2 - s1 * s1 * 0.1f) * (1.0f / 9.0f);
                sd[c][tt] = sqrtf(fmaxf(var, 0.f));
            }
        }

        float h1[5][7];
        const float* w1s = sm + OFF_SMALL + SW1;
#pragma unroll
        for (int o = 0; o < 5; ++o) {
            float bb = sm[OFF_SMALL + SB1 + o];
#pragma unroll
            for (int tt = 0; tt < 7; ++tt) h1[o][tt] = bb;
#pragma unroll
            for (int c = 0; c < 3; ++c)
#pragma unroll
                for (int k = 0; k < 3; ++k) {
                    float w = w1s[o * 9 + c * 3 + k];
#pragma unroll
                    for (int tt = 0; tt < 7; ++tt) h1[o][tt] += w * sd[c][tt + k];
                }
#pragma unroll
            for (int tt = 0; tt < 7; ++tt) h1[o][tt] = fmaxf(h1[o][tt], 0.f);
        }

        const float* w2s = sm + OFF_SMALL + SW2;
        float* ftT = sm + OFF_FEAT;
#pragma unroll
        for (int o = 0; o < 10; ++o) {
            float a2[5];
            float bb = sm[OFF_SMALL + SB2 + o];
#pragma unroll
            for (int tt = 0; tt < 5; ++tt) a2[tt] = bb;
#pragma unroll
            for (int i = 0; i < 5; ++i)
#pragma unroll
                for (int k = 0; k < 3; ++k) {
                    float w = w2s[o * 15 + i * 3 + k];
#pragma unroll
                    for (int tt = 0; tt < 5; ++tt) a2[tt] += w * h1[i][tt + k];
                }
#pragma unroll
            for (int tt = 0; tt < 5; ++tt)
                if (t0 + tt < 36)
                    ftT[((t0 + tt) * 10 + o) * FPAD + s] = fmaxf(a2[tt], 0.f);
        }
    }

    // ---- fc1: 360 -> 256 ----
    // thread: 4 outputs o = ol*4 + j (contiguous -> one LDS.128 weight load),
    //         8 samples (4 f32x2 pairs, mg group), acts warp-broadcast.
    const int ob = ol * 4;
    ull acc[4][4];
#pragma unroll
    for (int j = 0; j < 4; ++j) {
        float b = sm[OFF_SMALL + SFB1 + ob + j];
        ull pb2 = pack2(b, b);
#pragma unroll
        for (int p = 0; p < 4; ++p) acc[p][j] = pb2;
    }

    float4 pf[6];
    {
        const float4* g = (const float4*)(fw1 + tid * 360);
#pragma unroll
        for (int i = 0; i < 6; ++i) pf[i] = g[i];
    }
    __syncthreads();   // featurize done; wbuf (signal) free for weights
    {
        float* wb = sm + OFF_WBUF;
#pragma unroll
        for (int i = 0; i < 6; ++i) {
            wb[(i * 4 + 0) * 256 + tid] = pf[i].x;
            wb[(i * 4 + 1) * 256 + tid] = pf[i].y;
            wb[(i * 4 + 2) * 256 + tid] = pf[i].z;
            wb[(i * 4 + 3) * 256 + tid] = pf[i].w;
        }
    }
    __syncthreads();

#pragma unroll 1
    for (int c = 0; c < 15; ++c) {
        if (c < 14) {
            const float4* g = (const float4*)(fw1 + tid * 360 + (c + 1) * 24);
#pragma unroll
            for (int i = 0; i < 6; ++i) pf[i] = g[i];
        }
        const float* wb = sm + OFF_WBUF + (c & 1) * 6144;
        const float* ft = sm + OFF_FEAT + c * 24 * FPAD + mg * 8;
#pragma unroll 8
        for (int kk = 0; kk < 24; ++kk) {
            ull a0, a1, a2, a3;
            ld2x2(ft + kk * FPAD,     a0, a1);
            ld2x2(ft + kk * FPAD + 4, a2, a3);
            float4 wv = *(const float4*)(wb + kk * 256 + ob);
            ull w0 = dup(wv.x), w1d = dup(wv.y), w2d = dup(wv.z), w3d = dup(wv.w);
            fma2(acc[0][0], a0, w0);  fma2(acc[1][0], a1, w0);
            fma2(acc[2][0], a2, w0);  fma2(acc[3][0], a3, w0);
            fma2(acc[0][1], a0, w1d); fma2(acc[1][1], a1, w1d);
            fma2(acc[2][1], a2, w1d); fma2(acc[3][1], a3, w1d);
            fma2(acc[0][2], a0, w2d); fma2(acc[1][2], a1, w2d);
            fma2(acc[2][2], a2, w2d); fma2(acc[3][2], a3, w2d);
            fma2(acc[0][3], a0, w3d); fma2(acc[1][3], a1, w3d);
            fma2(acc[2][3], a2, w3d); fma2(acc[3][3], a3, w3d);
        }
        if (c < 14) {
            __syncthreads();
            float* wbn = sm + OFF_WBUF + ((c + 1) & 1) * 6144;
#pragma unroll
            for (int i = 0; i < 6; ++i) {
                wbn[(i * 4 + 0) * 256 + tid] = pf[i].x;
                wbn[(i * 4 + 1) * 256 + tid] = pf[i].y;
                wbn[(i * 4 + 2) * 256 + tid] = pf[i].z;
                wbn[(i * 4 + 3) * 256 + tid] = pf[i].w;
            }
            __syncthreads();
        }
    }

    // ---- relu + redistribute f1 (transposed, j-rotated to spread banks) ----
    __syncthreads();
    {
        float* f1T = sm + OFF_FEAT;
        const int rot = tid & 3;
#pragma unroll
        for (int jj = 0; jj < 4; ++jj) {
            const int j = (jj + rot) & 3;
            const int o = ob + j;
#pragma unroll
            for (int p = 0; p < 4; ++p) {
                float2 v = unpk(acc[p][j]);
                v.x = fmaxf(v.x, 0.f); v.y = fmaxf(v.y, 0.f);
                *(float2*)(f1T + o * FPAD + mg * 8 + p * 2) = v;
            }
        }
    }
    __syncthreads();

    // ---- fc2: 256 -> 64 ----  (thread: 1 output o=ol, 4 sample pairs)
    ull acc2[4];
    {
        float b = sm[OFF_SMALL + SFB2 + ol];
        ull pb2 = pack2(b, b);
#pragma unroll
        for (int p = 0; p < 4; ++p) acc2[p] = pb2;
    }
    float4 pf2[2];
    const int kq = tid >> 6;  // k-quarter within chunk
    {
        const float4* g = (const float4*)(fw2 + ol * 256 + kq * 8);
        pf2[0] = g[0]; pf2[1] = g[1];
    }
    {
        float* wb2 = sm + OFF_WBUF;
#pragma unroll
        for (int i = 0; i < 2; ++i) {
            const int kk = kq * 8 + i * 4;
            wb2[(kk + 0) * 64 + ol] = pf2[i].x;
            wb2[(kk + 1) * 64 + ol] = pf2[i].y;
            wb2[(kk + 2) * 64 + ol] = pf2[i].z;
            wb2[(kk + 3) * 64 + ol] = pf2[i].w;
        }
    }
    __syncthreads();

#pragma unroll 1
    for (int c = 0; c < 8; ++c) {
        if (c < 7) {
            const float4* g = (const float4*)(fw2 + ol * 256 + (c + 1) * 32 + kq * 8);
            pf2[0] = g[0]; pf2[1] = g[1];
        }
        const float* wb2 = sm + OFF_WBUF + (c & 1) * 2048;
        const float* ft  = sm + OFF_FEAT + c * 32 * FPAD + mg * 8;
#pragma unroll 8
        for (int kk = 0; kk < 32; ++kk) {
            ull a0, a1, a2, a3;
            ld2x2(ft + kk * FPAD,     a0, a1);
            ld2x2(ft + kk * FPAD + 4, a2, a3);
            ull w = dup(wb2[kk * 64 + ol]);
            fma2(acc2[0], a0, w); fma2(acc2[1], a1, w);
            fma2(acc2[2], a2, w); fma2(acc2[3], a3, w);
        }
        if (c < 7) {
            __syncthreads();
            float* wbn = sm + OFF_WBUF + ((c + 1) & 1) * 2048;
#pragma unroll
            for (int i = 0; i < 2; ++i) {
                const int kk = kq * 8 + i * 4;
                wbn[(kk + 0) * 64 + ol] = pf2[i].x;
                wbn[(kk + 1) * 64 + ol] = pf2[i].y;
                wbn[(kk + 2) * 64 + ol] = pf2[i].z;
                wbn[(kk + 3) * 64 + ol] = pf2[i].w;
            }
            __syncthreads();
        }
    }

    // ---- relu + redistribute f2 (transposed) ----
    __syncthreads();
    {
        float* f2T = sm + OFF_FEAT;
#pragma unroll
        for (int p = 0; p < 4; ++p) {
            float2 v = unpk(acc2[p]);
            v.x = fmaxf(v.x, 0.f); v.y = fmaxf(v.y, 0.f);
            *(float2*)(f2T + ol * FPAD + mg * 8 + p * 2) = v;
        }
    }
    __syncthreads();

    // ---- head (64 -> 12) + log_softmax : one thread per sample ----
    if (tid < NS) {
        const float* f2T = sm + OFF_FEAT;
        const float* pws = sm + OFF_SMALL + SPW;
        float l[12];
#pragma unroll
        for (int j = 0; j < 12; ++j) l[j] = sm[OFF_SMALL + SPB + j];
        for (int k = 0; k < 64; ++k) {
            float v = f2T[k * FPAD + tid];
#pragma unroll
            for (int j = 0; j < 12; ++j) l[j] += v * pws[j * 64 + k];
        }
        float m = l[0];
#pragma unroll
        for (int j = 1; j < 12; ++j) m = fmaxf(m, l[j]);
        float ssum = 0.f;
#pragma unroll
        for (int j = 0; j < 12; ++j) ssum += expf(l[j] - m);
        float lse = m + logf(ssum);
        float* op = out + ((size_t)bx * NS + tid) * 12;
#pragma unroll
        for (int j = 0; j < 12; ++j) op[j] = l[j] - lse;
    }
}

extern "C" void kernel_launch(void* const* d_in, const int* in_sizes, int n_in,
                              void* d_out, int out_size)
{
    (void)n_in; (void)out_size;
    const float* sig = (const float*)d_in[0];
    const float* w1  = (const float*)d_in[1];
    const float* b1  = (const float*)d_in[2];
    const float* w2  = (const float*)d_in[3];
    const float* b2  = (const float*)d_in[4];
    const float* fw1 = (const float*)d_in[5];
    const float* fb1 = (const float*)d_in[6];
    const float* fw2 = (const float*)d_in[7];
    const float* fb2 = (const float*)d_in[8];
    const float* pw  = (const float*)d_in[9];
    const float* pb  = (const float*)d_in[10];
    float* out = (float*)d_out;

    const int B = in_sizes[0] / 150;        // (B, 50, 3)
    const int nblocks = B / NS;             // 131072 / 32 = 4096

    cudaFuncSetAttribute(convnet_fused_kernel,
                         cudaFuncAttributeMaxDynamicSharedMemorySize, SMBYTES);
    convnet_fused_kernel<<<nblocks, NT, SMBYTES>>>(
        sig, w1, b1, w2, b2, fw1, fb1, fw2, fb2, pw, pb, out);
}

// round 4
// speedup vs baseline: 1.0004x; 1.0004x over previous
#include <cuda_runtime.h>
#include <cstdint>

#define NS 32      // samples per block
#define NT 256     // threads per block
#define FPAD 36    // padded row stride (floats) for featT / f1T / f2T (mult of 4)

// SMEM float offsets
#define OFF_WBUF 0                        // 12288 floats: fc1 dbl-buf (2x6144); also signal tile (4800) & fc2 dbl-buf (2x2048)
#define OFF_FEAT 12288                    // 12960 floats: featT[360][36] -> f1T[256][36] -> f2T[64][36]
#define OFF_SMALL (12288 + 12960)         // small consts
#define SM_FLOATS (OFF_SMALL + 1312)
#define SMBYTES (SM_FLOATS * 4)           // 106240 B -> 2 CTAs/SM

// small-const layout within OFF_SMALL
#define SW1 0      // conv1_w 45
#define SB1 45     // conv1_b 5
#define SW2 50     // conv2_w 150
#define SB2 200    // conv2_b 10
#define SFB1 210   // fc1_b 256
#define SFB2 466   // fc2_b 64
#define SPW 530    // pamap_w 768
#define SPB 1298   // pamap_b 12

typedef unsigned long long ull;

__device__ __forceinline__ ull pack2(float x, float y) {
    ull v; asm("mov.b64 %0, {%1, %2};" : "=l"(v) : "f"(x), "f"(y)); return v;
}
__device__ __forceinline__ float2 unpk(ull v) {
    float2 r; asm("mov.b64 {%0, %1}, %2;" : "=f"(r.x), "=f"(r.y) : "l"(v)); return r;
}
// duplicate scalar into packed pair (ALU pipe; avoids duplicated weights in smem)
__device__ __forceinline__ ull dup(float w) {
    ull v; asm("mov.b64 %0, {%1, %1};" : "=l"(v) : "f"(w)); return v;
}
// d = a * b + d  (packed 2x fp32, Blackwell FFMA2)
__device__ __forceinline__ void fma2(ull& d, ull a, ull b) {
    asm("fma.rn.f32x2 %0, %1, %2, %0;" : "+l"(d) : "l"(a), "l"(b));
}
// 16B shared load -> two packed f32 pairs
__device__ __forceinline__ void ld2x2(const float* p, ull& a, ull& b) {
    unsigned ad = (unsigned)__cvta_generic_to_shared(p);
    asm volatile("ld.shared.v2.u64 {%0, %1}, [%2];" : "=l"(a), "=l"(b) : "r"(ad));
}

__global__ __launch_bounds__(NT, 2)
void convnet_fused_kernel(const float* __restrict__ sig,
                          const float* __restrict__ w1, const float* __restrict__ b1,
                          const float* __restrict__ w2, const float* __restrict__ b2,
                          const float* __restrict__ fw1, const float* __restrict__ fb1,
                          const float* __restrict__ fw2, const float* __restrict__ fb2,
                          const float* __restrict__ pw, const float* __restrict__ pb,
                          float* __restrict__ out)
{
    extern __shared__ float sm[];
    const int tid = threadIdx.x;
    const int bx  = blockIdx.x;
    const int ol  = tid & 63;   // 64 output-lane groups
    const int mg  = tid >> 6;   // sample group (8 samples = 4 pairs), warp-uniform

    // ---- stage small constants ----
    for (int i = tid; i < 45;  i += NT) sm[OFF_SMALL + SW1 + i] = w1[i];
    if (tid < 5)                         sm[OFF_SMALL + SB1 + tid] = b1[tid];
    for (int i = tid; i < 150; i += NT) sm[OFF_SMALL + SW2 + i] = w2[i];
    if (tid < 10)                        sm[OFF_SMALL + SB2 + tid] = b2[tid];
    sm[OFF_SMALL + SFB1 + tid] = fb1[tid];
    if (tid < 64)                        sm[OFF_SMALL + SFB2 + tid] = fb2[tid];
    for (int i = tid; i < 768; i += NT) sm[OFF_SMALL + SPW + i] = pw[i];
    if (tid < 12)                        sm[OFF_SMALL + SPB + tid] = pb[tid];

    // ---- load signal tile: 32 samples x 150 floats ----
    {
        const float4* g = (const float4*)(sig + (size_t)bx * NS * 150);
        float4* s4 = (float4*)(sm + OFF_WBUF);
        for (int i = tid; i < NS * 150 / 4; i += NT) s4[i] = g[i];
    }
    __syncthreads();

    // ---- featurize: running_std -> conv1 -> conv2 -> featT[k][sample] ----
    {
        const int s  = tid & 31;
        const int t0 = (tid >> 5) * 5;            // 8 threads/sample, 5 t's each
        const float* xs = sm + OFF_WBUF + s * 150;

        float sd[3][9];
#pragma unroll
        for (int c = 0; c < 3; ++c) {
            float xr[18];
#pragma unroll
            for (int j = 0; j < 18; ++j) xr[j] = xs[(t0 + j) * 3 + c];
#pragma unroll
            for (int tt = 0; tt < 9; ++tt) {
                float s1 = 0.f, s2 = 0.f;
#pragma unroll
                for (int j = 0; j < 10; ++j) { float v = xr[tt + j]; s1 += v; s2 += v * v; }
                float var = (s2 - s1 * s1 * 0.1f) * (1.0f / 9.0f);
                sd[c][tt] = sqrtf(fmaxf(var, 0.f));
            }
        }

        float h1[5][7];
        const float* w1s = sm + OFF_SMALL + SW1;
#pragma unroll
        for (int o = 0; o < 5; ++o) {
            float bb = sm[OFF_SMALL + SB1 + o];
#pragma unroll
            for (int tt = 0; tt < 7; ++tt) h1[o][tt] = bb;
#pragma unroll
            for (int c = 0; c < 3; ++c)
#pragma unroll
                for (int k = 0; k < 3; ++k) {
                    float w = w1s[o * 9 + c * 3 + k];
#pragma unroll
                    for (int tt = 0; tt < 7; ++tt) h1[o][tt] += w * sd[c][tt + k];
                }
#pragma unroll
            for (int tt = 0; tt < 7; ++tt) h1[o][tt] = fmaxf(h1[o][tt], 0.f);
        }

        const float* w2s = sm + OFF_SMALL + SW2;
        float* ftT = sm + OFF_FEAT;
#pragma unroll
        for (int o = 0; o < 10; ++o) {
            float a2[5];
            float bb = sm[OFF_SMALL + SB2 + o];
#pragma unroll
            for (int tt = 0; tt < 5; ++tt) a2[tt] = bb;
#pragma unroll
            for (int i = 0; i < 5; ++i)
#pragma unroll
                for (int k = 0; k < 3; ++k) {
                    float w = w2s[o * 15 + i * 3 + k];
#pragma unroll
                    for (int tt = 0; tt < 5; ++tt) a2[tt] += w * h1[i][tt + k];
                }
#pragma unroll
            for (int tt = 0; tt < 5; ++tt)
                if (t0 + tt < 36)
                    ftT[((t0 + tt) * 10 + o) * FPAD + s] = fmaxf(a2[tt], 0.f);
        }
    }

    // ---- fc1: 360 -> 256 ----
    // thread: 4 outputs o = ol*4 + j (contiguous -> one LDS.128 weight load),
    //         8 samples (4 f32x2 pairs, mg group), acts warp-broadcast.
    const int ob = ol * 4;
    ull acc[4][4];
#pragma unroll
    for (int j = 0; j < 4; ++j) {
        float b = sm[OFF_SMALL + SFB1 + ob + j];
        ull pb2 = pack2(b, b);
#pragma unroll
        for (int p = 0; p < 4; ++p) acc[p][j] = pb2;
    }

    float4 pf[6];
    {
        const float4* g = (const float4*)(fw1 + tid * 360);
#pragma unroll
        for (int i = 0; i < 6; ++i) pf[i] = g[i];
    }
    __syncthreads();   // featurize done; wbuf (signal) free for weights
    {
        float* wb = sm + OFF_WBUF;
#pragma unroll
        for (int i = 0; i < 6; ++i) {
            wb[(i * 4 + 0) * 256 + tid] = pf[i].x;
            wb[(i * 4 + 1) * 256 + tid] = pf[i].y;
            wb[(i * 4 + 2) * 256 + tid] = pf[i].z;
            wb[(i * 4 + 3) * 256 + tid] = pf[i].w;
        }
    }
    __syncthreads();

#pragma unroll 1
    for (int c = 0; c < 15; ++c) {
        if (c < 14) {
            const float4* g = (const float4*)(fw1 + tid * 360 + (c + 1) * 24);
#pragma unroll
            for (int i = 0; i < 6; ++i) pf[i] = g[i];
        }
        const float* wb = sm + OFF_WBUF + (c & 1) * 6144;
        const float* ft = sm + OFF_FEAT + c * 24 * FPAD + mg * 8;
#pragma unroll 8
        for (int kk = 0; kk < 24; ++kk) {
            ull a0, a1, a2, a3;
            ld2x2(ft + kk * FPAD,     a0, a1);
            ld2x2(ft + kk * FPAD + 4, a2, a3);
            float4 wv = *(const float4*)(wb + kk * 256 + ob);
            ull w0 = dup(wv.x), w1d = dup(wv.y), w2d = dup(wv.z), w3d = dup(wv.w);
            fma2(acc[0][0], a0, w0);  fma2(acc[1][0], a1, w0);
            fma2(acc[2][0], a2, w0);  fma2(acc[3][0], a3, w0);
            fma2(acc[0][1], a0, w1d); fma2(acc[1][1], a1, w1d);
            fma2(acc[2][1], a2, w1d); fma2(acc[3][1], a3, w1d);
            fma2(acc[0][2], a0, w2d); fma2(acc[1][2], a1, w2d);
            fma2(acc[2][2], a2, w2d); fma2(acc[3][2], a3, w2d);
            fma2(acc[0][3], a0, w3d); fma2(acc[1][3], a1, w3d);
            fma2(acc[2][3], a2, w3d); fma2(acc[3][3], a3, w3d);
        }
        if (c < 14) {
            __syncthreads();
            float* wbn = sm + OFF_WBUF + ((c + 1) & 1) * 6144;
#pragma unroll
            for (int i = 0; i < 6; ++i) {
                wbn[(i * 4 + 0) * 256 + tid] = pf[i].x;
                wbn[(i * 4 + 1) * 256 + tid] = pf[i].y;
                wbn[(i * 4 + 2) * 256 + tid] = pf[i].z;
                wbn[(i * 4 + 3) * 256 + tid] = pf[i].w;
            }
            __syncthreads();
        }
    }

    // ---- relu + redistribute f1 (transposed, j-rotated to spread banks) ----
    __syncthreads();
    {
        float* f1T = sm + OFF_FEAT;
        const int rot = tid & 3;
#pragma unroll
        for (int jj = 0; jj < 4; ++jj) {
            const int j = (jj + rot) & 3;
            const int o = ob + j;
#pragma unroll
            for (int p = 0; p < 4; ++p) {
                float2 v = unpk(acc[p][j]);
                v.x = fmaxf(v.x, 0.f); v.y = fmaxf(v.y, 0.f);
                *(float2*)(f1T + o * FPAD + mg * 8 + p * 2) = v;
            }
        }
    }
    __syncthreads();

    // ---- fc2: 256 -> 64 ----  (thread: 1 output o=ol, 4 sample pairs)
    ull acc2[4];
    {
        float b = sm[OFF_SMALL + SFB2 + ol];
        ull pb2 = pack2(b, b);
#pragma unroll
        for (int p = 0; p < 4; ++p) acc2[p] = pb2;
    }
    float4 pf2[2];
    const int kq = tid >> 6;  // k-quarter within chunk
    {
        const float4* g = (const float4*)(fw2 + ol * 256 + kq * 8);
        pf2[0] = g[0]; pf2[1] = g[1];
    }
    {
        float* wb2 = sm + OFF_WBUF;
#pragma unroll
        for (int i = 0; i < 2; ++i) {
            const int kk = kq * 8 + i * 4;
            wb2[(kk + 0) * 64 + ol] = pf2[i].x;
            wb2[(kk + 1) * 64 + ol] = pf2[i].y;
            wb2[(kk + 2) * 64 + ol] = pf2[i].z;
            wb2[(kk + 3) * 64 + ol] = pf2[i].w;
        }
    }
    __syncthreads();

#pragma unroll 1
    for (int c = 0; c < 8; ++c) {
        if (c < 7) {
            const float4* g = (const float4*)(fw2 + ol * 256 + (c + 1) * 32 + kq * 8);
            pf2[0] = g[0]; pf2[1] = g[1];
        }
        const float* wb2 = sm + OFF_WBUF + (c & 1) * 2048;
        const float* ft  = sm + OFF_FEAT + c * 32 * FPAD + mg * 8;
#pragma unroll 8
        for (int kk = 0; kk < 32; ++kk) {
            ull a0, a1, a2, a3;
            ld2x2(ft + kk * FPAD,     a0, a1);
            ld2x2(ft + kk * FPAD + 4, a2, a3);
            ull w = dup(wb2[kk * 64 + ol]);
            fma2(acc2[0], a0, w); fma2(acc2[1], a1, w);
            fma2(acc2[2], a2, w); fma2(acc2[3], a3, w);
        }
        if (c < 7) {
            __syncthreads();
            float* wbn = sm + OFF_WBUF + ((c + 1) & 1) * 2048;
#pragma unroll
            for (int i = 0; i < 2; ++i) {
                const int kk = kq * 8 + i * 4;
                wbn[(kk + 0) * 64 + ol] = pf2[i].x;
                wbn[(kk + 1) * 64 + ol] = pf2[i].y;
                wbn[(kk + 2) * 64 + ol] = pf2[i].z;
                wbn[(kk + 3) * 64 + ol] = pf2[i].w;
            }
            __syncthreads();
        }
    }

    // ---- relu + redistribute f2 (transposed) ----
    __syncthreads();
    {
        float* f2T = sm + OFF_FEAT;
#pragma unroll
        for (int p = 0; p < 4; ++p) {
            float2 v = unpk(acc2[p]);
            v.x = fmaxf(v.x, 0.f); v.y = fmaxf(v.y, 0.f);
            *(float2*)(f2T + ol * FPAD + mg * 8 + p * 2) = v;
        }
    }
    __syncthreads();

    // ---- head (64 -> 12) + log_softmax : one thread per sample ----
    if (tid < NS) {
        const float* f2T = sm + OFF_FEAT;
        const float* pws = sm + OFF_SMALL + SPW;
        float l[12];
#pragma unroll
        for (int j = 0; j < 12; ++j) l[j] = sm[OFF_SMALL + SPB + j];
        for (int k = 0; k < 64; ++k) {
            float v = f2T[k * FPAD + tid];
#pragma unroll
            for (int j = 0; j < 12; ++j) l[j] += v * pws[j * 64 + k];
        }
        float m = l[0];
#pragma unroll
        for (int j = 1; j < 12; ++j) m = fmaxf(m, l[j]);
        float ssum = 0.f;
#pragma unroll
        for (int j = 0; j < 12; ++j) ssum += expf(l[j] - m);
        float lse = m + logf(ssum);
        float* op = out + ((size_t)bx * NS + tid) * 12;
#pragma unroll
        for (int j = 0; j < 12; ++j) op[j] = l[j] - lse;
    }
}

extern "C" void kernel_launch(void* const* d_in, const int* in_sizes, int n_in,
                              void* d_out, int out_size)
{
    (void)n_in; (void)out_size;
    const float* sig = (const float*)d_in[0];
    const float* w1  = (const float*)d_in[1];
    const float* b1  = (const float*)d_in[2];
    const float* w2  = (const float*)d_in[3];
    const float* b2  = (const float*)d_in[4];
    const float* fw1 = (const float*)d_in[5];
    const float* fb1 = (const float*)d_in[6];
    const float* fw2 = (const float*)d_in[7];
    const float* fb2 = (const float*)d_in[8];
    const float* pw  = (const float*)d_in[9];
    const float* pb  = (const float*)d_in[10];
    float* out = (float*)d_out;

    const int B = in_sizes[0] / 150;        // (B, 50, 3)
    const int nblocks = B / NS;             // 131072 / 32 = 4096

    cudaFuncSetAttribute(convnet_fused_kernel,
                         cudaFuncAttributeMaxDynamicSharedMemorySize, SMBYTES);
    convnet_fused_kernel<<<nblocks, NT, SMBYTES>>>(
        sig, w1, b1, w2, b2, fw1, fb1, fw2, fb2, pw, pb, out);
}

// round 6
// speedup vs baseline: 2.0082x; 2.0074x over previous
#include <cuda_runtime.h>
#include <cuda_bf16.h>
#include <cstdint>

typedef unsigned int u32;

#define NT 256
// smem byte offsets
#define O_SC   0
#define O_A1H  5376
#define O_A1L  55552
#define O_W    105728
#define O_A2H  5376
#define O_A2L  39168
#define O_F2   72960
#define SMB    146688
// const float indices
#define SW1 0
#define SB1 45
#define SW2 50
#define SB2 200
#define SFB1 210
#define SFB2 466
#define SPW 530
#define SPB 1298

// prep output: fc1 [24 chunks][256 n][40 k] (ch 0-11 hi, 12-23 lo), fc2 [16][64][40]
__device__ __align__(16) __nv_bfloat16 g_w1p[24 * 256 * 40];
__device__ __align__(16) __nv_bfloat16 g_w2p[16 * 64 * 40];

__device__ __forceinline__ u32 smem_u32(const void* p) {
    u32 a; asm("{ .reg .u64 t; cvta.to.shared.u64 t, %1; cvt.u32.u64 %0, t; }" : "=r"(a) : "l"(p)); return a;
}
__device__ __forceinline__ u32 lds32(u32 a) {
    u32 v; asm volatile("ld.shared.b32 %0,[%1];" : "=r"(v) : "r"(a)); return v;
}
__device__ __forceinline__ void mma_bf16(float* d, u32 a0, u32 a1, u32 a2, u32 a3, u32 b0, u32 b1) {
    asm volatile("mma.sync.aligned.m16n8k16.row.col.f32.bf16.bf16.f32 "
                 "{%0,%1,%2,%3},{%4,%5,%6,%7},{%8,%9},{%0,%1,%2,%3};"
                 : "+f"(d[0]), "+f"(d[1]), "+f"(d[2]), "+f"(d[3])
                 : "r"(a0), "r"(a1), "r"(a2), "r"(a3), "r"(b0), "r"(b1));
}
// split (a,b) into hi-pair (returned) and lo-pair (out)
__device__ __forceinline__ u32 split2(float a, float b, u32& lo) {
    __nv_bfloat16 ha = __float2bfloat16(a), hb = __float2bfloat16(b);
    float ra = a - __bfloat162float(ha), rb = b - __bfloat162float(hb);
    lo = ((u32)__bfloat16_as_ushort(__float2bfloat16(rb)) << 16)
       | (u32)__bfloat16_as_ushort(__float2bfloat16(ra));
    return ((u32)__bfloat16_as_ushort(hb) << 16) | (u32)__bfloat16_as_ushort(ha);
}

__global__ void prep_kernel(const float* __restrict__ fw1, const float* __restrict__ fw2) {
    int i = blockIdx.x * 256 + threadIdx.x;
    if (i < 24 * 256 * 40) {
        int ch = i / 10240, rem = i % 10240, n = rem / 40, pos = rem % 40;
        int k = (ch % 12) * 32 + pos;
        float v = (pos < 32 && k < 360) ? fw1[n * 360 + k] : 0.0f;
        __nv_bfloat16 h = __float2bfloat16(v);
        g_w1p[i] = (ch < 12) ? h : __float2bfloat16(v - __bfloat162float(h));
    }
    if (i < 16 * 64 * 40) {
        int ch = i / 2560, rem = i % 2560, n = rem / 40, pos = rem % 40;
        int k = (ch % 8) * 32 + pos;
        float v = (pos < 32) ? fw2[n * 256 + k] : 0.0f;
        __nv_bfloat16 h = __float2bfloat16(v);
        g_w2p[i] = (ch < 8) ? h : __float2bfloat16(v - __bfloat162float(h));
    }
}

__global__ __launch_bounds__(NT)
void convnet_mma_kernel(const float* __restrict__ sig,
                        const float* __restrict__ w1, const float* __restrict__ b1,
                        const float* __restrict__ w2, const float* __restrict__ b2,
                        const float* __restrict__ fb1, const float* __restrict__ fb2,
                        const float* __restrict__ pw, const float* __restrict__ pb,
                        float* __restrict__ out)
{
    extern __shared__ char smem[];
    const int tid = threadIdx.x, lane = tid & 31, wid = tid >> 5, bx = blockIdx.x;
    const int g = lane >> 2, q = lane & 3;
    const int warpm = wid & 3, warpn = wid >> 2;
    const u32 sb = smem_u32(smem);
    float* SC = (float*)(smem + O_SC);

    // stage small consts
    for (int i = tid; i < 45; i += NT)  SC[SW1 + i] = w1[i];
    if (tid < 5)  SC[SB1 + tid] = b1[tid];
    for (int i = tid; i < 150; i += NT) SC[SW2 + i] = w2[i];
    if (tid < 10) SC[SB2 + tid] = b2[tid];
    SC[SFB1 + tid] = fb1[tid];
    if (tid < 64) SC[SFB2 + tid] = fb2[tid];
    for (int i = tid; i < 768; i += NT) SC[SPW + i] = pw[i];
    if (tid < 12) SC[SPB + tid] = pb[tid];
    // stage signal tile (64 x 150 f32) into W region
    {
        const float4* gsig = (const float4*)(sig + (size_t)bx * 64 * 150);
        float4* s4 = (float4*)(smem + O_W);
        for (int i = tid; i < 64 * 150 / 4; i += NT) s4[i] = gsig[i];
    }
    __syncthreads();

    // ---- featurize -> A1 hi/lo bf16, row-major [64][392] ----
    {
        const int s = tid & 63, t0 = (tid >> 6) * 9;
        const float* xs = (const float*)(smem + O_W) + s * 150;
        float xv[3][23];
#pragma unroll
        for (int j = 0; j < 23; ++j)
#pragma unroll
            for (int c = 0; c < 3; ++c) xv[c][j] = xs[(t0 + j) * 3 + c];
        float sd[3][13];
#pragma unroll
        for (int c = 0; c < 3; ++c)
#pragma unroll
            for (int tt = 0; tt < 13; ++tt) {
                float s1 = 0.f, s2 = 0.f;
#pragma unroll
                for (int j = 0; j < 10; ++j) { float v = xv[c][tt + j]; s1 += v; s2 += v * v; }
                sd[c][tt] = sqrtf(fmaxf((s2 - s1 * s1 * 0.1f) * (1.0f / 9.0f), 0.f));
            }
        float h1[5][11];
#pragma unroll
        for (int o = 0; o < 5; ++o) {
            float bb = SC[SB1 + o];
#pragma unroll
            for (int tt = 0; tt < 11; ++tt) h1[o][tt] = bb;
#pragma unroll
            for (int c = 0; c < 3; ++c)
#pragma unroll
                for (int k = 0; k < 3; ++k) {
                    float w = SC[SW1 + o * 9 + c * 3 + k];
#pragma unroll
                    for (int tt = 0; tt < 11; ++tt) h1[o][tt] += w * sd[c][tt + k];
                }
#pragma unroll
            for (int tt = 0; tt < 11; ++tt) h1[o][tt] = fmaxf(h1[o][tt], 0.f);
        }
        __nv_bfloat16* A1h = (__nv_bfloat16*)(smem + O_A1H);
        __nv_bfloat16* A1l = (__nv_bfloat16*)(smem + O_A1L);
#pragma unroll
        for (int o = 0; o < 10; ++o) {
            float a2[9];
            float bb = SC[SB2 + o];
#pragma unroll
            for (int tt = 0; tt < 9; ++tt) a2[tt] = bb;
#pragma unroll
            for (int i = 0; i < 5; ++i)
#pragma unroll
                for (int k = 0; k < 3; ++k) {
                    float w = SC[SW2 + o * 15 + i * 3 + k];
#pragma unroll
                    for (int tt = 0; tt < 9; ++tt) a2[tt] += w * h1[i][tt + k];
                }
#pragma unroll
            for (int tt = 0; tt < 9; ++tt) {
                float v = fmaxf(a2[tt], 0.f);
                int k = (t0 + tt) * 10 + o;
                __nv_bfloat16 h = __float2bfloat16(v);
                A1h[s * 392 + k] = h;
                A1l[s * 392 + k] = __float2bfloat16(v - __bfloat162float(h));
            }
        }
    }
    // zero K pad 360..383
    for (int i = tid; i < 64 * 24; i += NT) {
        int s = i / 24, k = 360 + i % 24;
        ((__nv_bfloat16*)(smem + O_A1H))[s * 392 + k] = __float2bfloat16(0.f);
        ((__nv_bfloat16*)(smem + O_A1L))[s * 392 + k] = __float2bfloat16(0.f);
    }
    __syncthreads();

    // ---- fc1: 64x256, K=384, 3-term hi/lo ----
    float acc[64];
#pragma unroll
    for (int i = 0; i < 64; ++i) acc[i] = 0.f;

    const uint4* wp1 = (const uint4*)g_w1p;   // 1280 uint4 per chunk
    uint4 wr[5];
#pragma unroll
    for (int j = 0; j < 5; ++j) wr[j] = wp1[tid + j * 256];
    {
        uint4* wb = (uint4*)(smem + O_W);
#pragma unroll
        for (int j = 0; j < 5; ++j) wb[tid + j * 256] = wr[j];
    }
    __syncthreads();

    const u32 aHb = sb + O_A1H + (u32)(warpm * 16 + g) * 784 + q * 4;
    const u32 aLb = sb + O_A1L + (u32)(warpm * 16 + g) * 784 + q * 4;
    const u32 bB  = sb + O_W + (u32)(warpn * 128 + g) * 80 + q * 4;

#pragma unroll 1
    for (int ch = 0; ch < 24; ++ch) {
        if (ch < 23) {
            const uint4* p = wp1 + (ch + 1) * 1280;
#pragma unroll
            for (int j = 0; j < 5; ++j) wr[j] = p[tid + j * 256];
        }
        const u32 bbase = bB + (u32)(ch & 1) * 20480;
        const int kof = ((ch < 12) ? ch : (ch - 12)) * 32;
        const bool both = (ch < 12);
#pragma unroll
        for (int ks = 0; ks < 2; ++ks) {
            const u32 ao = (u32)(kof + ks * 16) * 2;
            u32 ah0 = lds32(aHb + ao),        ah1 = lds32(aHb + 6272 + ao);
            u32 ah2 = lds32(aHb + ao + 16),   ah3 = lds32(aHb + 6272 + ao + 16);
            u32 al0 = 0, al1 = 0, al2 = 0, al3 = 0;
            if (both) {
                al0 = lds32(aLb + ao);      al1 = lds32(aLb + 6272 + ao);
                al2 = lds32(aLb + ao + 16); al3 = lds32(aLb + 6272 + ao + 16);
            }
#pragma unroll
            for (int nt = 0; nt < 16; ++nt) {
                u32 ba = bbase + nt * 640 + ks * 32;
                u32 b0 = lds32(ba), b1 = lds32(ba + 16);
                mma_bf16(acc + nt * 4, ah0, ah1, ah2, ah3, b0, b1);
                if (both) mma_bf16(acc + nt * 4, al0, al1, al2, al3, b0, b1);
            }
        }
        __syncthreads();
        if (ch < 23) {
            uint4* wb = (uint4*)(smem + O_W + ((ch + 1) & 1) * 20480);
#pragma unroll
            for (int j = 0; j < 5; ++j) wb[tid + j * 256] = wr[j];
            __syncthreads();
        }
    }

    // ---- fc1 epilogue: bias+relu+split -> A2 hi/lo [64][264] ----
    {
        const int r0 = warpm * 16 + g;
#pragma unroll
        for (int nt = 0; nt < 16; ++nt) {
            const int n0 = warpn * 128 + nt * 8 + q * 2;
            float bb0 = SC[SFB1 + n0], bb1 = SC[SFB1 + n0 + 1];
            float v0 = fmaxf(acc[nt * 4 + 0] + bb0, 0.f), v1 = fmaxf(acc[nt * 4 + 1] + bb1, 0.f);
            float v2 = fmaxf(acc[nt * 4 + 2] + bb0, 0.f), v3 = fmaxf(acc[nt * 4 + 3] + bb1, 0.f);
            u32 lo, hi;
            hi = split2(v0, v1, lo);
            *(u32*)(smem + O_A2H + r0 * 528 + n0 * 2) = hi;
            *(u32*)(smem + O_A2L + r0 * 528 + n0 * 2) = lo;
            hi = split2(v2, v3, lo);
            *(u32*)(smem + O_A2H + (r0 + 8) * 528 + n0 * 2) = hi;
            *(u32*)(smem + O_A2L + (r0 + 8) * 528 + n0 * 2) = lo;
        }
    }
    __syncthreads();

    // ---- fc2: 64x64, K=256, 3-term ----
#pragma unroll
    for (int i = 0; i < 16; ++i) acc[i] = 0.f;
    const uint4* wp2 = (const uint4*)g_w2p;   // 320 uint4 per chunk
    uint4 w2a; uint4 w2b = make_uint4(0, 0, 0, 0);
    w2a = wp2[tid];
    if (tid < 64) w2b = wp2[256 + tid];
    {
        uint4* wb = (uint4*)(smem + O_W);
        wb[tid] = w2a;
        if (tid < 64) wb[256 + tid] = w2b;
    }
    __syncthreads();

    const u32 a2Hb = sb + O_A2H + (u32)(warpm * 16 + g) * 528 + q * 4;
    const u32 a2Lb = sb + O_A2L + (u32)(warpm * 16 + g) * 528 + q * 4;
    const u32 b2B  = sb + O_W + (u32)(warpn * 32 + g) * 80 + q * 4;

#pragma unroll 1
    for (int ch = 0; ch < 16; ++ch) {
        if (ch < 15) {
            const uint4* p = wp2 + (ch + 1) * 320;
            w2a = p[tid];
            if (tid < 64) w2b = p[256 + tid];
        }
        const u32 bbase = b2B + (u32)(ch & 1) * 20480;
        const int kof = (ch & 7) * 32;
        const bool both = (ch < 8);
#pragma unroll
        for (int ks = 0; ks < 2; ++ks) {
            const u32 ao = (u32)(kof + ks * 16) * 2;
            u32 ah0 = lds32(a2Hb + ao),      ah1 = lds32(a2Hb + 4224 + ao);
            u32 ah2 = lds32(a2Hb + ao + 16), ah3 = lds32(a2Hb + 4224 + ao + 16);
            u32 al0 = 0, al1 = 0, al2 = 0, al3 = 0;
            if (both) {
                al0 = lds32(a2Lb + ao);      al1 = lds32(a2Lb + 4224 + ao);
                al2 = lds32(a2Lb + ao + 16); al3 = lds32(a2Lb + 4224 + ao + 16);
            }
#pragma unroll
            for (int nt = 0; nt < 4; ++nt) {
                u32 ba = bbase + nt * 640 + ks * 32;
                u32 b0 = lds32(ba), b1 = lds32(ba + 16);
                mma_bf16(acc + nt * 4, ah0, ah1, ah2, ah3, b0, b1);
                if (both) mma_bf16(acc + nt * 4, al0, al1, al2, al3, b0, b1);
            }
        }
        __syncthreads();
        if (ch < 15) {
            uint4* wb = (uint4*)(smem + O_W + ((ch + 1) & 1) * 20480);
            wb[tid] = w2a;
            if (tid < 64) wb[256 + tid] = w2b;
            __syncthreads();
        }
    }

    // ---- fc2 epilogue -> f2 [64][69] f32 ----
    {
        float* f2 = (float*)(smem + O_F2);
        const int r0 = warpm * 16 + g;
#pragma unroll
        for (int nt = 0; nt < 4; ++nt) {
            const int n0 = warpn * 32 + nt * 8 + q * 2;
            float bb0 = SC[SFB2 + n0], bb1 = SC[SFB2 + n0 + 1];
            f2[r0 * 69 + n0]           = fmaxf(acc[nt * 4 + 0] + bb0, 0.f);
            f2[r0 * 69 + n0 + 1]       = fmaxf(acc[nt * 4 + 1] + bb1, 0.f);
            f2[(r0 + 8) * 69 + n0]     = fmaxf(acc[nt * 4 + 2] + bb0, 0.f);
            f2[(r0 + 8) * 69 + n0 + 1] = fmaxf(acc[nt * 4 + 3] + bb1, 0.f);
        }
    }
    __syncthreads();

    // ---- head (64->12) + log_softmax ----
    if (tid < 64) {
        const float* f2 = (const float*)(smem + O_F2) + tid * 69;
        float l[12];
#pragma unroll
        for (int j = 0; j < 12; ++j) l[j] = SC[SPB + j];
#pragma unroll 8
        for (int k = 0; k < 64; ++k) {
            float v = f2[k];
#pragma unroll
            for (int j = 0; j < 12; ++j) l[j] += v * SC[SPW + j * 64 + k];
        }
        float m = l[0];
#pragma unroll
        for (int j = 1; j < 12; ++j) m = fmaxf(m, l[j]);
        float ssum = 0.f;
#pragma unroll
        for (int j = 0; j < 12; ++j) ssum += expf(l[j] - m);
        float lse = m + logf(ssum);
        float* op = out + ((size_t)bx * 64 + tid) * 12;
#pragma unroll
        for (int j = 0; j < 12; ++j) op[j] = l[j] - lse;
    }
}

extern "C" void kernel_launch(void* const* d_in, const int* in_sizes, int n_in,
                              void* d_out, int out_size)
{
    (void)n_in; (void)out_size;
    const float* sig = (const float*)d_in[0];
    const float* w1  = (const float*)d_in[1];
    const float* b1  = (const float*)d_in[2];
    const float* w2  = (const float*)d_in[3];
    const float* b2  = (const float*)d_in[4];
    const float* fw1 = (const float*)d_in[5];
    const float* fb1 = (const float*)d_in[6];
    const float* fw2 = (const float*)d_in[7];
    const float* fb2 = (const float*)d_in[8];
    const float* pw  = (const float*)d_in[9];
    const float* pb  = (const float*)d_in[10];
    float* out = (float*)d_out;

    const int B = in_sizes[0] / 150;
    prep_kernel<<<960, 256>>>(fw1, fw2);
    cudaFuncSetAttribute(convnet_mma_kernel, cudaFuncAttributeMaxDynamicSharedMemorySize, SMB);
    convnet_mma_kernel<<<B / 64, NT, SMB>>>(sig, w1, b1, w2, b2, fb1, fb2, pw, pb, out);
}

// round 7
// speedup vs baseline: 2.2399x; 1.1154x over previous
#include <cuda_runtime.h>
#include <cuda_bf16.h>
#include <cstdint>

typedef unsigned int u32;

#define NT 256
// smem byte offsets
#define O_SC   0
#define O_A1H  5376
#define O_A1L  55552
#define O_W    105728
#define O_A2H  5376
#define O_A2L  39168
#define O_F2   72960
#define SMB    146688
// const float indices
#define SW1 0
#define SB1 45
#define SW2 50
#define SB2 200
#define SFB1 210
#define SFB2 466
#define SPW 530
#define SPB 1298

// prep output: fc1 [24 chunks][256 n][40 k] (ch 0-11 hi, 12-23 lo), fc2 [16][64][40]
__device__ __align__(16) __nv_bfloat16 g_w1p[24 * 256 * 40];
__device__ __align__(16) __nv_bfloat16 g_w2p[16 * 64 * 40];

__device__ __forceinline__ u32 smem_u32(const void* p) {
    u32 a; asm("{ .reg .u64 t; cvta.to.shared.u64 t, %1; cvt.u32.u64 %0, t; }" : "=r"(a) : "l"(p)); return a;
}
__device__ __forceinline__ void ldm4(u32 a, u32* d) {
    asm volatile("ldmatrix.sync.aligned.m8n8.x4.shared.b16 {%0,%1,%2,%3},[%4];"
                 : "=r"(d[0]), "=r"(d[1]), "=r"(d[2]), "=r"(d[3]) : "r"(a));
}
__device__ __forceinline__ void mma_bf16(float* d, const u32* a, u32 b0, u32 b1) {
    asm volatile("mma.sync.aligned.m16n8k16.row.col.f32.bf16.bf16.f32 "
                 "{%0,%1,%2,%3},{%4,%5,%6,%7},{%8,%9},{%0,%1,%2,%3};"
                 : "+f"(d[0]), "+f"(d[1]), "+f"(d[2]), "+f"(d[3])
                 : "r"(a[0]), "r"(a[1]), "r"(a[2]), "r"(a[3]), "r"(b0), "r"(b1));
}
__device__ __forceinline__ u32 split2(float a, float b, u32& lo) {
    __nv_bfloat16 ha = __float2bfloat16(a), hb = __float2bfloat16(b);
    float ra = a - __bfloat162float(ha), rb = b - __bfloat162float(hb);
    lo = ((u32)__bfloat16_as_ushort(__float2bfloat16(rb)) << 16)
       | (u32)__bfloat16_as_ushort(__float2bfloat16(ra));
    return ((u32)__bfloat16_as_ushort(hb) << 16) | (u32)__bfloat16_as_ushort(ha);
}

__global__ void prep_kernel(const float* __restrict__ fw1, const float* __restrict__ fw2) {
    int i = blockIdx.x * 256 + threadIdx.x;
    if (i < 24 * 256 * 40) {
        int ch = i / 10240, rem = i % 10240, n = rem / 40, pos = rem % 40;
        int k = (ch % 12) * 32 + pos;
        float v = (pos < 32 && k < 360) ? fw1[n * 360 + k] : 0.0f;
        __nv_bfloat16 h = __float2bfloat16(v);
        g_w1p[i] = (ch < 12) ? h : __float2bfloat16(v - __bfloat162float(h));
    }
    if (i < 16 * 64 * 40) {
        int ch = i / 2560, rem = i % 2560, n = rem / 40, pos = rem % 40;
        int k = (ch % 8) * 32 + pos;
        float v = (pos < 32) ? fw2[n * 256 + k] : 0.0f;
        __nv_bfloat16 h = __float2bfloat16(v);
        g_w2p[i] = (ch < 8) ? h : __float2bfloat16(v - __bfloat162float(h));
    }
}

__global__ __launch_bounds__(NT)
void convnet_mma_kernel(const float* __restrict__ sig,
                        const float* __restrict__ w1, const float* __restrict__ b1,
                        const float* __restrict__ w2, const float* __restrict__ b2,
                        const float* __restrict__ fb1, const float* __restrict__ fb2,
                        const float* __restrict__ pw, const float* __restrict__ pb,
                        float* __restrict__ out)
{
    extern __shared__ char smem[];
    const int tid = threadIdx.x, lane = tid & 31, wid = tid >> 5, bx = blockIdx.x;
    const int g = lane >> 2, q = lane & 3;
    const int warpm = wid & 3, warpn = wid >> 2;
    const int lrow = lane & 7, lsel = lane >> 3;
    const u32 sb = smem_u32(smem);
    float* SC = (float*)(smem + O_SC);

    // stage small consts
    for (int i = tid; i < 45; i += NT)  SC[SW1 + i] = w1[i];
    if (tid < 5)  SC[SB1 + tid] = b1[tid];
    for (int i = tid; i < 150; i += NT) SC[SW2 + i] = w2[i];
    if (tid < 10) SC[SB2 + tid] = b2[tid];
    SC[SFB1 + tid] = fb1[tid];
    if (tid < 64) SC[SFB2 + tid] = fb2[tid];
    for (int i = tid; i < 768; i += NT) SC[SPW + i] = pw[i];
    if (tid < 12) SC[SPB + tid] = pb[tid];
    // stage signal tile (64 x 150 f32) into W region
    {
        const float4* gsig = (const float4*)(sig + (size_t)bx * 64 * 150);
        float4* s4 = (float4*)(smem + O_W);
        for (int i = tid; i < 64 * 150 / 4; i += NT) s4[i] = gsig[i];
    }
    __syncthreads();

    // ---- featurize -> A1 hi/lo bf16, row-major [64][392] ----
    {
        const int s = tid & 63, t0 = (tid >> 6) * 9;
        const float* xs = (const float*)(smem + O_W) + s * 150;
        float xv[3][23];
#pragma unroll
        for (int j = 0; j < 23; ++j)
#pragma unroll
            for (int c = 0; c < 3; ++c) xv[c][j] = xs[(t0 + j) * 3 + c];
        float sd[3][13];
#pragma unroll
        for (int c = 0; c < 3; ++c)
#pragma unroll
            for (int tt = 0; tt < 13; ++tt) {
                float s1 = 0.f, s2 = 0.f;
#pragma unroll
                for (int j = 0; j < 10; ++j) { float v = xv[c][tt + j]; s1 += v; s2 += v * v; }
                sd[c][tt] = sqrtf(fmaxf((s2 - s1 * s1 * 0.1f) * (1.0f / 9.0f), 0.f));
            }
        float h1[5][11];
#pragma unroll
        for (int o = 0; o < 5; ++o) {
            float bb = SC[SB1 + o];
#pragma unroll
            for (int tt = 0; tt < 11; ++tt) h1[o][tt] = bb;
#pragma unroll
            for (int c = 0; c < 3; ++c)
#pragma unroll
                for (int k = 0; k < 3; ++k) {
                    float w = SC[SW1 + o * 9 + c * 3 + k];
#pragma unroll
                    for (int tt = 0; tt < 11; ++tt) h1[o][tt] += w * sd[c][tt + k];
                }
#pragma unroll
            for (int tt = 0; tt < 11; ++tt) h1[o][tt] = fmaxf(h1[o][tt], 0.f);
        }
        __nv_bfloat16* A1h = (__nv_bfloat16*)(smem + O_A1H);
        __nv_bfloat16* A1l = (__nv_bfloat16*)(smem + O_A1L);
#pragma unroll
        for (int o = 0; o < 10; ++o) {
            float a2[9];
            float bb = SC[SB2 + o];
#pragma unroll
            for (int tt = 0; tt < 9; ++tt) a2[tt] = bb;
#pragma unroll
            for (int i = 0; i < 5; ++i)
#pragma unroll
                for (int k = 0; k < 3; ++k) {
                    float w = SC[SW2 + o * 15 + i * 3 + k];
#pragma unroll
                    for (int tt = 0; tt < 9; ++tt) a2[tt] += w * h1[i][tt + k];
                }
#pragma unroll
            for (int tt = 0; tt < 9; ++tt) {
                float v = fmaxf(a2[tt], 0.f);
                int k = (t0 + tt) * 10 + o;
                __nv_bfloat16 h = __float2bfloat16(v);
                A1h[s * 392 + k] = h;
                A1l[s * 392 + k] = __float2bfloat16(v - __bfloat162float(h));
            }
        }
    }
    // zero K pad 360..383
    for (int i = tid; i < 64 * 24; i += NT) {
        int s = i / 24, k = 360 + i % 24;
        ((__nv_bfloat16*)(smem + O_A1H))[s * 392 + k] = __float2bfloat16(0.f);
        ((__nv_bfloat16*)(smem + O_A1L))[s * 392 + k] = __float2bfloat16(0.f);
    }
    __syncthreads();

    // ---- fc1: 64x256, K=384, 3-term hi/lo, ldmatrix fragments ----
    float acc[64];
#pragma unroll
    for (int i = 0; i < 64; ++i) acc[i] = 0.f;

    const uint4* wp1 = (const uint4*)g_w1p;   // 1280 uint4 per chunk
    uint4 wr[5];
#pragma unroll
    for (int j = 0; j < 5; ++j) wr[j] = wp1[tid + j * 256];
    {
        uint4* wb = (uint4*)(smem + O_W);
#pragma unroll
        for (int j = 0; j < 5; ++j) wb[tid + j * 256] = wr[j];
    }
    __syncthreads();

    // ldmatrix per-lane base addresses
    const u32 a1H = sb + O_A1H
        + (u32)((warpm * 16 + lrow + (lsel & 1) * 8) * 784 + ((lsel >> 1) & 1) * 16);
    const u32 a1L = a1H + (u32)(O_A1L - O_A1H);
    const u32 b1B = (u32)((warpn * 128 + lrow + ((lsel >> 1) & 1) * 8) * 80 + (lsel & 1) * 16);

#pragma unroll 1
    for (int ch = 0; ch < 24; ++ch) {
        if (ch < 23) {
            const uint4* p = wp1 + (ch + 1) * 1280;
#pragma unroll
            for (int j = 0; j < 5; ++j) wr[j] = p[tid + j * 256];
        }
        const u32 bb = sb + O_W + (u32)(ch & 1) * 20480 + b1B;
        const u32 kof2 = (u32)(((ch < 12) ? ch : (ch - 12)) * 64);
        const bool both = (ch < 12);
#pragma unroll
        for (int ks = 0; ks < 2; ++ks) {
            u32 ah[4], al[4];
            ldm4(a1H + kof2 + ks * 32, ah);
            if (both) ldm4(a1L + kof2 + ks * 32, al);
#pragma unroll
            for (int pr = 0; pr < 8; ++pr) {
                u32 b[4];
                ldm4(bb + pr * 1280 + ks * 32, b);
                mma_bf16(acc + pr * 8,     ah, b[0], b[1]);
                mma_bf16(acc + pr * 8 + 4, ah, b[2], b[3]);
                if (both) {
                    mma_bf16(acc + pr * 8,     al, b[0], b[1]);
                    mma_bf16(acc + pr * 8 + 4, al, b[2], b[3]);
                }
            }
        }
        if (ch < 23) {
            uint4* wb = (uint4*)(smem + O_W + ((ch + 1) & 1) * 20480);
#pragma unroll
            for (int j = 0; j < 5; ++j) wb[tid + j * 256] = wr[j];
            __syncthreads();
        }
    }
    __syncthreads();   // all warps done reading A1 before A2 overwrites it

    // ---- fc1 epilogue: bias+relu+split -> A2 hi/lo [64][264] ----
    {
        const int r0 = warpm * 16 + g;
#pragma unroll
        for (int nt = 0; nt < 16; ++nt) {
            const int n0 = warpn * 128 + nt * 8 + q * 2;
            float bb0 = SC[SFB1 + n0], bb1 = SC[SFB1 + n0 + 1];
            float v0 = fmaxf(acc[nt * 4 + 0] + bb0, 0.f), v1 = fmaxf(acc[nt * 4 + 1] + bb1, 0.f);
            float v2 = fmaxf(acc[nt * 4 + 2] + bb0, 0.f), v3 = fmaxf(acc[nt * 4 + 3] + bb1, 0.f);
            u32 lo, hi;
            hi = split2(v0, v1, lo);
            *(u32*)(smem + O_A2H + r0 * 528 + n0 * 2) = hi;
            *(u32*)(smem + O_A2L + r0 * 528 + n0 * 2) = lo;
            hi = split2(v2, v3, lo);
            *(u32*)(smem + O_A2H + (r0 + 8) * 528 + n0 * 2) = hi;
            *(u32*)(smem + O_A2L + (r0 + 8) * 528 + n0 * 2) = lo;
        }
    }
    __syncthreads();

    // ---- fc2: 64x64, K=256, 3-term ----
#pragma unroll
    for (int i = 0; i < 16; ++i) acc[i] = 0.f;
    const uint4* wp2 = (const uint4*)g_w2p;   // 320 uint4 per chunk
    uint4 w2a; uint4 w2b = make_uint4(0, 0, 0, 0);
    w2a = wp2[tid];
    if (tid < 64) w2b = wp2[256 + tid];
    {
        uint4* wb = (uint4*)(smem + O_W);
        wb[tid] = w2a;
        if (tid < 64) wb[256 + tid] = w2b;
    }
    __syncthreads();

    const u32 a2H = sb + O_A2H
        + (u32)((warpm * 16 + lrow + (lsel & 1) * 8) * 528 + ((lsel >> 1) & 1) * 16);
    const u32 a2L = a2H + (u32)(O_A2L - O_A2H);
    const u32 b2B = (u32)((warpn * 32 + lrow + ((lsel >> 1) & 1) * 8) * 80 + (lsel & 1) * 16);

#pragma unroll 1
    for (int ch = 0; ch < 16; ++ch) {
        if (ch < 15) {
            const uint4* p = wp2 + (ch + 1) * 320;
            w2a = p[tid];
            if (tid < 64) w2b = p[256 + tid];
        }
        const u32 bb = sb + O_W + (u32)(ch & 1) * 20480 + b2B;
        const u32 kof2 = (u32)((ch & 7) * 64);
        const bool both = (ch < 8);
#pragma unroll
        for (int ks = 0; ks < 2; ++ks) {
            u32 ah[4], al[4];
            ldm4(a2H + kof2 + ks * 32, ah);
            if (both) ldm4(a2L + kof2 + ks * 32, al);
#pragma unroll
            for (int pr = 0; pr < 2; ++pr) {
                u32 b[4];
                ldm4(bb + pr * 1280 + ks * 32, b);
                mma_bf16(acc + pr * 8,     ah, b[0], b[1]);
                mma_bf16(acc + pr * 8 + 4, ah, b[2], b[3]);
                if (both) {
                    mma_bf16(acc + pr * 8,     al, b[0], b[1]);
                    mma_bf16(acc + pr * 8 + 4, al, b[2], b[3]);
                }
            }
        }
        if (ch < 15) {
            uint4* wb = (uint4*)(smem + O_W + ((ch + 1) & 1) * 20480);
            wb[tid] = w2a;
            if (tid < 64) wb[256 + tid] = w2b;
            __syncthreads();
        }
    }

    // ---- fc2 epilogue -> f2 [64][69] f32 (disjoint from A2 regions) ----
    {
        float* f2 = (float*)(smem + O_F2);
        const int r0 = warpm * 16 + g;
#pragma unroll
        for (int nt = 0; nt < 4; ++nt) {
            const int n0 = warpn * 32 + nt * 8 + q * 2;
            float bb0 = SC[SFB2 + n0], bb1 = SC[SFB2 + n0 + 1];
            f2[r0 * 69 + n0]           = fmaxf(acc[nt * 4 + 0] + bb0, 0.f);
            f2[r0 * 69 + n0 + 1]       = fmaxf(acc[nt * 4 + 1] + bb1, 0.f);
            f2[(r0 + 8) * 69 + n0]     = fmaxf(acc[nt * 4 + 2] + bb0, 0.f);
            f2[(r0 + 8) * 69 + n0 + 1] = fmaxf(acc[nt * 4 + 3] + bb1, 0.f);
        }
    }
    __syncthreads();

    // ---- head (64->12) + log_softmax ----
    if (tid < 64) {
        const float* f2 = (const float*)(smem + O_F2) + tid * 69;
        float l[12];
#pragma unroll
        for (int j = 0; j < 12; ++j) l[j] = SC[SPB + j];
#pragma unroll 8
        for (int k = 0; k < 64; ++k) {
            float v = f2[k];
#pragma unroll
            for (int j = 0; j < 12; ++j) l[j] += v * SC[SPW + j * 64 + k];
        }
        float m = l[0];
#pragma unroll
        for (int j = 1; j < 12; ++j) m = fmaxf(m, l[j]);
        float ssum = 0.f;
#pragma unroll
        for (int j = 0; j < 12; ++j) ssum += expf(l[j] - m);
        float lse = m + logf(ssum);
        float* op = out + ((size_t)bx * 64 + tid) * 12;
#pragma unroll
        for (int j = 0; j < 12; ++j) op[j] = l[j] - lse;
    }
}

extern "C" void kernel_launch(void* const* d_in, const int* in_sizes, int n_in,
                              void* d_out, int out_size)
{
    (void)n_in; (void)out_size;
    const float* sig = (const float*)d_in[0];
    const float* w1  = (const float*)d_in[1];
    const float* b1  = (const float*)d_in[2];
    const float* w2  = (const float*)d_in[3];
    const float* b2  = (const float*)d_in[4];
    const float* fw1 = (const float*)d_in[5];
    const float* fb1 = (const float*)d_in[6];
    const float* fw2 = (const float*)d_in[7];
    const float* fb2 = (const float*)d_in[8];
    const float* pw  = (const float*)d_in[9];
    const float* pb  = (const float*)d_in[10];
    float* out = (float*)d_out;

    const int B = in_sizes[0] / 150;
    prep_kernel<<<960, 256>>>(fw1, fw2);
    cudaFuncSetAttribute(convnet_mma_kernel, cudaFuncAttributeMaxDynamicSharedMemorySize, SMB);
    convnet_mma_kernel<<<B / 64, NT, SMB>>>(sig, w1, b1, w2, b2, fb1, fb2, pw, pb, out);
}